// round 7
// baseline (speedup 1.0000x reference)
#include <cuda_runtime.h>
#include <cstdint>

// ----------------------------------------------------------------------------
// Tropical (max-plus) ViT, fp32.  C[m,n] = max_k (A[m,k]+B[n,k]) everywhere.
// Round 6: cp.async double-buffered GEMM (no LDG front-batch, no STS
// transpose). All B operands k-major in gmem (weights transposed once,
// kT / v written by qkv epilogue). tau folded algebraically via wmax.
// ----------------------------------------------------------------------------

#define NEG_INF (-3.0e38f)
#define BB     8
#define NPATCH 196
#define DD     128
#define DFF    256
#define NPAD   224
#define MTOT   1568
#define NCLS   1000

// scratch
__device__ float g_h  [MTOT * DD];
__device__ float g_rmH[MTOT];
__device__ float g_q  [MTOT * DD];
__device__ float g_kT [BB * DD * NPAD];      // [b][d][j], j-pads stay 0
__device__ float g_v  [BB * NPAD * DD];      // [b][j][d], j>=196 rows stay 0
__device__ float g_s  [BB * NPATCH * NPAD];  // [b][i][j], j-pads = -inf
__device__ float g_p  [4][MTOT * DD];        // split-K parts
__device__ float g_h1 [MTOT * DFF];
__device__ float g_wT [262144];              // pooled transposed weights
__device__ float g_wmax[2][DD];
__device__ float g_wglob[2];
__device__ unsigned g_rmAtom[5][MTOT];
__device__ float g_pool[BB * DD];

// wT pool offsets
#define OFF_QKV 32768
#define OFF_F1  81920
#define OFF_F2  114688
#define LAY_STR 114688

enum { M_EMBED = 0, M_QKV = 1, M_SCORES = 2, M_ATT = 3, M_FF1 = 4, M_FF2 = 5 };

__device__ __forceinline__ unsigned f2ord(float f) {
    unsigned u = __float_as_uint(f);
    return u ^ ((unsigned)((int)u >> 31) | 0x80000000u);
}
__device__ __forceinline__ float ord2f(unsigned u) {
    unsigned v = (u & 0x80000000u) ? (u ^ 0x80000000u) : ~u;
    return __uint_as_float(v);
}
__device__ __forceinline__ void cpa(uint32_t d, const void* s) {
    asm volatile("cp.async.cg.shared.global [%0], [%1], 16;" :: "r"(d), "l"(s));
}

// ---------------------------------------------------------------------------
// Tropical NT GEMM: 32x32 tile, 128 threads, 2x4/thread.
// A [m][k] row-major (lda), Bt [k][n] k-major (ldb). cp.async 2-stage pipe.
// ---------------------------------------------------------------------------
template<int MODE>
__global__ __launch_bounds__(128) void tg(
    const float* __restrict__ A, const float* __restrict__ Bt,
    float* __restrict__ C0, float* __restrict__ C1,
    float* __restrict__ C2, float* __restrict__ C3,
    const float* __restrict__ rmSub, unsigned* __restrict__ rmAtom,
    const float* __restrict__ aux,
    int M, int N, int K, int lda, int ldb, int ldc,
    int aBatch, int bBatch, int cBatch, int splitShift, int kPerSplit)
{
    __shared__ __align__(16) float As[2][32][36];
    __shared__ __align__(16) float Bs[2][32][32];

    const int t  = threadIdx.x;
    const int tx = t & 7, ty = t >> 3;
    const int bm = blockIdx.y << 5, bn = blockIdx.x << 5;
    const int z = blockIdx.z;
    const int half  = z & ((1 << splitShift) - 1);
    const int batch = z >> splitShift;
    const int kBegin = half * kPerSplit;
    const int nc = (min(K, kBegin + kPerSplit) - kBegin) >> 5;   // 2..4 chunks

    // copy roles: thread -> (row 0..31, granule pair)
    const int crow = t >> 2;
    const int cg   = t & 3;

    const float* aSrc;
    {
        int ra = bm + crow; if (ra > M - 1) ra = M - 1;
        if (MODE == M_EMBED) {
            int b = ra / NPATCH, np = ra % NPATCH;
            aSrc = A + ((long)(b * 224 + (np / 14) * 16)) * 224 + (np % 14) * 16;
        } else {
            aSrc = A + (long)batch * aBatch + (long)ra * lda;
        }
    }
    const float* bSrc = Bt + (long)batch * bBatch + bn;

    const uint32_t aDst = (uint32_t)__cvta_generic_to_shared(&As[0][crow][cg * 4]);
    const uint32_t bDst = (uint32_t)__cvta_generic_to_shared(&Bs[0][crow][cg * 4]);
    const uint32_t A_STG = 32 * 36 * 4, B_STG = 32 * 32 * 4;

    auto issue = [&](int c) {
        const int st = c & 1;
        const int kk = kBegin + (c << 5);
#pragma unroll
        for (int i = 0; i < 2; ++i) {
            int kcol = kk + cg * 4 + i * 16;
            const float* s = (MODE == M_EMBED)
                ? aSrc + ((kcol >> 4) * 224 + (kcol & 15))
                : aSrc + kcol;
            cpa(aDst + st * A_STG + i * 64, s);
        }
#pragma unroll
        for (int i = 0; i < 2; ++i) {
            const float* s = bSrc + (long)(kk + crow) * ldb + cg * 4 + i * 16;
            cpa(bDst + st * B_STG + i * 64, s);
        }
        asm volatile("cp.async.commit_group;" ::: "memory");
    };

    float acc[2][4];
#pragma unroll
    for (int i = 0; i < 2; ++i)
#pragma unroll
        for (int j = 0; j < 4; ++j) acc[i][j] = NEG_INF;

    issue(0);
    if (nc > 1) issue(1);

    for (int c = 0; c < nc; ++c) {
        if (c + 1 < nc) asm volatile("cp.async.wait_group 1;" ::: "memory");
        else            asm volatile("cp.async.wait_group 0;" ::: "memory");
        __syncthreads();
        const int st = c & 1;
        const float* ar0 = &As[st][2 * ty][0];
        const float* ar1 = &As[st][2 * ty + 1][0];
#pragma unroll
        for (int k4 = 0; k4 < 8; ++k4) {
            float4 a0 = *(const float4*)(ar0 + k4 * 4);
            float4 a1 = *(const float4*)(ar1 + k4 * 4);
#pragma unroll
            for (int kk = 0; kk < 4; ++kk) {
                float4 b = *(const float4*)&Bs[st][k4 * 4 + kk][tx * 4];
                float x0 = (&a0.x)[kk], x1 = (&a1.x)[kk];
                acc[0][0] = fmaxf(acc[0][0], x0 + b.x);
                acc[0][1] = fmaxf(acc[0][1], x0 + b.y);
                acc[0][2] = fmaxf(acc[0][2], x0 + b.z);
                acc[0][3] = fmaxf(acc[0][3], x0 + b.w);
                acc[1][0] = fmaxf(acc[1][0], x1 + b.x);
                acc[1][1] = fmaxf(acc[1][1], x1 + b.y);
                acc[1][2] = fmaxf(acc[1][2], x1 + b.z);
                acc[1][3] = fmaxf(acc[1][3], x1 + b.w);
            }
        }
        if (c + 2 < nc) { __syncthreads(); issue(c + 2); }
    }

    // ---- epilogue ----
    float* Cs[4] = { C0, C1, C2, C3 };
    float rsub[2] = { 0.f, 0.f };
    if (MODE == M_QKV || MODE == M_FF1) {
        rsub[0] = rmSub[bm + 2 * ty];
        rsub[1] = rmSub[bm + 2 * ty + 1];
    }
    const bool atomicMode = (MODE == M_EMBED || MODE == M_ATT || MODE == M_FF2);
    float rmax2[2] = { NEG_INF, NEG_INF };

#pragma unroll
    for (int i = 0; i < 2; ++i) {
        int m = bm + 2 * ty + i;
        bool ok = (m < M);
#pragma unroll
        for (int j = 0; j < 4; ++j) {
            int n = bn + tx * 4 + j;
            float v = acc[i][j];
            if (MODE == M_EMBED) v += aux[(m % NPATCH) * DD + n];
            if (MODE == M_QKV || MODE == M_FF1) v -= rsub[i];
            if (atomicMode) rmax2[i] = fmaxf(rmax2[i], v);
            if (!ok) continue;
            if (MODE == M_QKV) {
                int b = m / NPATCH, ii = m % NPATCH;
                if (n < DD)            C0[(long)m * DD + n] = v;
                else if (n < 2 * DD)   C1[((long)b * DD + (n - DD)) * NPAD + ii] = v;
                else                   C2[((long)b * NPAD + ii) * DD + (n - 2 * DD)] = v;
            } else if (MODE == M_SCORES) {
                (C0 + (long)batch * cBatch)[(long)m * ldc + n] = (n < N) ? v : NEG_INF;
            } else if (MODE == M_FF1) {
                C0[(long)m * ldc + n] = v;
            } else { // EMBED / ATT / FF2 -> parts
                (Cs[half] + (long)batch * cBatch)[(long)m * ldc + n] = v;
            }
        }
    }

    if (atomicMode) {
#pragma unroll
        for (int i = 0; i < 2; ++i) {
            float rm = rmax2[i];
#pragma unroll
            for (int o = 1; o < 8; o <<= 1)
                rm = fmaxf(rm, __shfl_xor_sync(0xffffffffu, rm, o));
            int m = bm + 2 * ty + i;
            if (tx == 0 && m < M) {
                int row = (MODE == M_ATT) ? batch * NPATCH + m : m;
                atomicMax(&rmAtom[row], f2ord(rm));
            }
        }
    }
}

// ---------------------------------------------------------------------------
// one-shot weight transposes into g_wT (11 jobs, 256 tiles of 32x32)
// ---------------------------------------------------------------------------
struct TPtr { const float* s[11]; };

__global__ void transpose_k(TPtr tp)
{
    __shared__ float sm[32][33];
    static const int TS[11] = {0,32,48,64,80,112,144,160,176,192,224};
    static const int JC_[11] = {256,128,128,128,128,256,128,128,128,128,256};
    static const int JB_[11] = {0,OFF_QKV,OFF_QKV,OFF_QKV,OFF_F1,OFF_F2,
                                OFF_QKV+LAY_STR,OFF_QKV+LAY_STR,OFF_QKV+LAY_STR,
                                OFF_F1+LAY_STR,OFF_F2+LAY_STR};
    static const int JS_[11] = {128,384,384,384,256,128,384,384,384,256,128};
    static const int JO_[11] = {0,0,128,256,0,0,0,128,256,0,0};

    int bid = blockIdx.x;
    int j = 0;
#pragma unroll
    for (int i = 1; i < 11; ++i) j += (bid >= TS[i]);
    int lt = bid - TS[j];
    int C = JC_[j], S = JS_[j], base = JB_[j], co = JO_[j];
    int tC = C >> 5;
    int r0 = (lt / tC) << 5, c0 = (lt % tC) << 5;
    const float* src = tp.s[j];
    int rr = threadIdx.x >> 5, cc = threadIdx.x & 31;
#pragma unroll
    for (int i = 0; i < 4; ++i)
        sm[rr + 8 * i][cc] = src[(long)(r0 + rr + 8 * i) * C + c0 + cc];
    __syncthreads();
    float* dst = g_wT + base;
#pragma unroll
    for (int i = 0; i < 4; ++i)
        dst[(long)(c0 + rr + 8 * i) * S + co + r0 + cc] = sm[cc][rr + 8 * i];
}

// wmax[l][n] = max_k f2W[n,k]; wglob[l] = max_n wmax
__global__ void wmax_k(const float* __restrict__ w0, const float* __restrict__ w1)
{
    __shared__ float sm[4];
    int l = blockIdx.x, t = threadIdx.x;
    const float* w = (l ? w1 : w0) + (long)t * DFF;
    float m = NEG_INF;
#pragma unroll 4
    for (int k = 0; k < DFF; ++k) m = fmaxf(m, w[k]);
    g_wmax[l][t] = m;
    float r = m;
#pragma unroll
    for (int o = 16; o; o >>= 1) r = fmaxf(r, __shfl_xor_sync(0xffffffffu, r, o));
    if ((t & 31) == 0) sm[t >> 5] = r;
    __syncthreads();
    if (t == 0) g_wglob[l] = fmaxf(fmaxf(sm[0], sm[1]), fmaxf(sm[2], sm[3]));
}

// h = max4(parts); rmH = decode(atomic)
__global__ void combine4_k(const float* __restrict__ p0, const float* __restrict__ p1,
                           const float* __restrict__ p2, const float* __restrict__ p3,
                           const unsigned* __restrict__ rmSrc,
                           float* __restrict__ h, float* __restrict__ rmH)
{
    int r = blockIdx.x, t = threadIdx.x;
    long idx = (long)r * DD + t;
    h[idx] = fmaxf(fmaxf(p0[idx], p1[idx]), fmaxf(p2[idx], p3[idx]));
    if (t == 0) rmH[r] = ord2f(rmSrc[r]);
}

// h = max(h, max2(parts) - rm); rmH = max(rmH, 0)
__global__ void resid2_k(const float* __restrict__ p0, const float* __restrict__ p1,
                         const unsigned* __restrict__ rmA,
                         float* __restrict__ h, float* __restrict__ rmH)
{
    int r = blockIdx.x, t = threadIdx.x;
    long idx = (long)r * DD + t;
    float av = fmaxf(p0[idx], p1[idx]);
    h[idx] = fmaxf(h[idx], av - ord2f(rmA[r]));
    if (t == 0) rmH[r] = fmaxf(rmH[r], 0.f);
}

// ff residual with tau fold: ffout = max(max4(p), tau+wmax[n]); rm' includes tau term
__global__ void residff_k(const float* __restrict__ p0, const float* __restrict__ p1,
                          const float* __restrict__ p2, const float* __restrict__ p3,
                          const unsigned* __restrict__ rmA,
                          const float* __restrict__ wmax_l, const float* __restrict__ wglob_l,
                          const float* __restrict__ tau,
                          float* __restrict__ h, float* __restrict__ rmH)
{
    int r = blockIdx.x, t = threadIdx.x;
    long idx = (long)r * DD + t;
    float av = fmaxf(fmaxf(p0[idx], p1[idx]), fmaxf(p2[idx], p3[idx]));
    float tv = tau[0];
    float rm = fmaxf(ord2f(rmA[r]), tv + wglob_l[0]);
    h[idx] = fmaxf(h[idx], fmaxf(av, tv + wmax_l[t]) - rm);
    if (t == 0) rmH[r] = fmaxf(rmH[r], 0.f);
}

__global__ void pool_k()
{
    int b = blockIdx.x, t = threadIdx.x;
    float acc = NEG_INF;
    const float* base = g_h + (long)b * NPATCH * DD + t;
#pragma unroll 4
    for (int n = 0; n < NPATCH; ++n) acc = fmaxf(acc, base[(long)n * DD]);
    g_pool[b * DD + t] = acc;
}

__global__ void head_k(const float* __restrict__ W, const float* __restrict__ ls,
                       float* __restrict__ out)
{
    __shared__ float p[DD];
    int b = blockIdx.y, t = threadIdx.x;
    p[t] = g_pool[b * DD + t];
    __syncthreads();
    int c = blockIdx.x * 128 + t;
    if (c < NCLS) {
        float acc = NEG_INF;
        const float* w = W + (long)c * DD;
#pragma unroll 4
        for (int d = 0; d < DD; ++d) acc = fmaxf(acc, p[d] + w[d]);
        out[(long)b * NCLS + c] = acc * ls[0];
    }
}

// ---------------------------------------------------------------------------

extern "C" void kernel_launch(void* const* d_in, const int* in_sizes, int n_in,
                              void* d_out, int out_size)
{
    (void)in_sizes; (void)n_in; (void)out_size;
    const float* x       = (const float*)d_in[0];
    const float* embed_W = (const float*)d_in[1];
    const float* pos     = (const float*)d_in[2];
    const float* head_W  = (const float*)d_in[15];
    const float* lscale  = (const float*)d_in[16];
    float* out = (float*)d_out;

    float *h, *rmH, *q, *kT, *v, *s, *p, *h1, *wT, *wmax, *wglob;
    unsigned* rmA;
    cudaGetSymbolAddress((void**)&h,    g_h);
    cudaGetSymbolAddress((void**)&rmH,  g_rmH);
    cudaGetSymbolAddress((void**)&q,    g_q);
    cudaGetSymbolAddress((void**)&kT,   g_kT);
    cudaGetSymbolAddress((void**)&v,    g_v);
    cudaGetSymbolAddress((void**)&s,    g_s);
    cudaGetSymbolAddress((void**)&p,    g_p);
    cudaGetSymbolAddress((void**)&h1,   g_h1);
    cudaGetSymbolAddress((void**)&wT,   g_wT);
    cudaGetSymbolAddress((void**)&wmax, g_wmax);
    cudaGetSymbolAddress((void**)&wglob,g_wglob);
    cudaGetSymbolAddress((void**)&rmA,  g_rmAtom);

    float *p1 = p + MTOT * DD, *p2 = p + 2 * MTOT * DD, *p3 = p + 3 * MTOT * DD;

    // one-shot: transpose weights, wmax, reset atomics
    TPtr tp;
    tp.s[0] = embed_W;
    for (int l = 0; l < 2; ++l) {
        tp.s[1 + 5 * l] = (const float*)d_in[3 + 6 * l];   // qW
        tp.s[2 + 5 * l] = (const float*)d_in[4 + 6 * l];   // kW
        tp.s[3 + 5 * l] = (const float*)d_in[5 + 6 * l];   // vW
        tp.s[4 + 5 * l] = (const float*)d_in[6 + 6 * l];   // f1W
        tp.s[5 + 5 * l] = (const float*)d_in[7 + 6 * l];   // f2W
    }
    transpose_k<<<256, 256>>>(tp);
    wmax_k<<<2, 128>>>((const float*)d_in[7], (const float*)d_in[13]);
    cudaMemsetAsync(rmA, 0, 5 * MTOT * sizeof(unsigned));

    // embed: patchify fused, K=256 split4 -> parts + atomic rowmax
    tg<M_EMBED><<<dim3(4, 49, 4), 128>>>(x, wT, p, p1, p2, p3,
        0, rmA, pos, MTOT, DD, 256, 0, DD, DD, 0, 0, 0, 2, 64);
    combine4_k<<<MTOT, 128>>>(p, p1, p2, p3, rmA, h, rmH);

    for (int l = 0; l < 2; ++l) {
        const float* tau = (const float*)d_in[8 + 6 * l];
        unsigned* rmAt = rmA + (1 + 2 * l) * MTOT;
        unsigned* rmFf = rmA + (2 + 2 * l) * MTOT;
        const float* qkvWT = wT + OFF_QKV + l * LAY_STR;
        const float* f1WT  = wT + OFF_F1  + l * LAY_STR;
        const float* f2WT  = wT + OFF_F2  + l * LAY_STR;

        // q/k/v fused (N=384): epilogue subtracts rmH; writes q, kT, v
        tg<M_QKV><<<dim3(12, 49, 1), 128>>>(h, qkvWT, q, kT, v, 0,
            rmH, 0, 0, MTOT, 384, DD, DD, 384, DD, 0, 0, 0, 0, DD);

        // scores per batch: A=q, Bt=kT; pads -> -inf
        tg<M_SCORES><<<dim3(7, 7, 8), 128>>>(q, kT, s, 0, 0, 0,
            0, 0, 0, NPATCH, NPATCH, DD, DD, NPAD, NPAD,
            NPATCH * DD, DD * NPAD, NPATCH * NPAD, 0, DD);

        // attn out per batch: A=s, Bt=v; K=224 split2 -> p0/p1 + atomic rowmax
        tg<M_ATT><<<dim3(4, 7, 16), 128>>>(s, v, p, p1, 0, 0,
            0, rmAt, 0, NPATCH, DD, NPAD, NPAD, DD, DD,
            NPATCH * NPAD, NPAD * DD, NPATCH * DD, 1, 128);
        resid2_k<<<MTOT, 128>>>(p, p1, rmAt, h, rmH);

        // ff1: epilogue subtracts rmH -> h1 (tau folded into residff via wmax)
        tg<M_FF1><<<dim3(8, 49, 1), 128>>>(h, f1WT, h1, 0, 0, 0,
            rmH, 0, 0, MTOT, DFF, DD, DD, DFF, DFF, 0, 0, 0, 0, DD);

        // ff2: A=h1 raw; K=256 split4 -> parts + atomic rowmax (tau term in residff)
        tg<M_FF2><<<dim3(4, 49, 4), 128>>>(h1, f2WT, p, p1, p2, p3,
            0, rmFf, 0, MTOT, DD, DFF, DFF, DD, DD, 0, 0, 0, 2, 64);
        residff_k<<<MTOT, 128>>>(p, p1, p2, p3, rmFf,
            wmax + l * DD, wglob + l, tau, h, rmH);
    }

    pool_k<<<BB, 128>>>();
    head_k<<<dim3(8, BB), 128>>>(head_W, lscale, out);
}

// round 8
// speedup vs baseline: 1.1624x; 1.1624x over previous
#include <cuda_runtime.h>

// ----------------------------------------------------------------------------
// Tropical (max-plus) ViT, fp32.  C[m,n] = max_k (A[m,k]+B[n,k]) everywhere.
// Round 7: round-3 GEMM loop (best measured) + atomic rowmax epilogues,
// xn eliminated (epilogue subtract), pool folded into last residual,
// single-pass barrier-free followers.
// ----------------------------------------------------------------------------

#define NEG_INF (-3.0e38f)
#define BB     8
#define NPATCH 196
#define DD     128
#define DFF    256
#define NPAD   224
#define MTOT   1568
#define NCLS   1000

__device__ float g_h  [MTOT * DD];
__device__ float g_rmH[MTOT];
__device__ float g_q  [MTOT * DD];
__device__ float g_k  [MTOT * DD];
__device__ float g_vT [BB * DD * NPAD];      // [b][d][j], j-pads stay 0
__device__ float g_s  [BB * NPATCH * NPAD];  // [b][i][j], j-pads = -inf
__device__ float g_p  [2][MTOT * DD];        // split-K parts
__device__ float g_h1 [MTOT * DFF];
// atomics: [0..5*MTOT) rowmax (embed, att0, ff0, att1, ff1), then pool
__device__ unsigned g_atoms[5 * MTOT + BB * DD];

enum { M_EMBED, M_QKV, M_SCORES, M_ATT, M_FF1, M_FF2 };

__device__ __forceinline__ unsigned f2ord(float f) {
    unsigned u = __float_as_uint(f);
    return u ^ ((unsigned)((int)u >> 31) | 0x80000000u);
}
__device__ __forceinline__ float ord2f(unsigned u) {
    unsigned v = (u & 0x80000000u) ? (u ^ 0x80000000u) : ~u;
    return __uint_as_float(v);
}

// ---------------------------------------------------------------------------
// Tropical NT GEMM: 32x32 block tile, 128 threads, 2x4 per thread.
// A: [M,K] row stride K; B: [N,K] row stride K.  (round-3 loop, unchanged)
// ---------------------------------------------------------------------------
template<int MODE>
__global__ __launch_bounds__(128) void tg(
    const float* __restrict__ A, const float* __restrict__ B,
    const float* __restrict__ B2, const float* __restrict__ B3,
    float* __restrict__ C0, float* __restrict__ C1, float* __restrict__ C2,
    const float* __restrict__ rmSub, unsigned* __restrict__ rmAtom,
    const float* __restrict__ aux,
    int M, int N, int K, int ldc,
    int aBatch, int bBatch, int cBatch,
    int splitShift, int kPerSplit)
{
    __shared__ __align__(16) float As[32][34];
    __shared__ __align__(16) float Bs[32][36];

    const int t  = threadIdx.x;
    const int tx = t & 7;          // n group (4 cols)
    const int ty = t >> 3;         // m group (2 rows)
    const int lk = tx << 2;
    const int lr = ty;
    const int bm = blockIdx.y << 5;
    const int bn = blockIdx.x << 5;

    const int z      = blockIdx.z;
    const int half   = z & ((1 << splitShift) - 1);
    const int batch  = z >> splitShift;
    const int kBegin = half * kPerSplit;
    const int kEnd   = min(K, kBegin + kPerSplit);

    const float* Ab = A + (long)batch * aBatch;
    const float* Bb = B + (long)batch * bBatch;

    const float* arow[2];
#pragma unroll
    for (int h = 0; h < 2; ++h) {
        int ra = bm + lr + 16 * h; if (ra > M - 1) ra = M - 1;
        if (MODE == M_EMBED) {
            int b = ra / NPATCH, np = ra % NPATCH;
            arow[h] = A + ((long)(b * 224 + (np / 14) * 16)) * 224 + (np % 14) * 16;
        } else {
            arow[h] = Ab + (long)ra * K;
        }
    }
    const float* brow[2];
#pragma unroll
    for (int h = 0; h < 2; ++h) {
        int rb = bn + lr + 16 * h; if (rb > N - 1) rb = N - 1;
        if (MODE == M_QKV) {
            const float* Bp = rb < 128 ? B : (rb < 256 ? B2 : B3);
            brow[h] = Bp + (long)(rb & 127) * K;
        } else {
            brow[h] = Bb + (long)rb * K;
        }
    }

    float acc[2][4];
#pragma unroll
    for (int i = 0; i < 2; ++i)
#pragma unroll
        for (int j = 0; j < 4; ++j) acc[i][j] = NEG_INF;

    for (int kk = kBegin; kk < kEnd; kk += 32) {
#pragma unroll
        for (int h = 0; h < 2; ++h) {
            float4 va;
            if (MODE == M_EMBED) {
                int j = kk + lk; int pr = j >> 4, pc = j & 15;
                va = *(const float4*)(arow[h] + pr * 224 + pc);
            } else {
                va = *(const float4*)(arow[h] + kk + lk);
            }
            As[lk + 0][lr + 16 * h] = va.x;
            As[lk + 1][lr + 16 * h] = va.y;
            As[lk + 2][lr + 16 * h] = va.z;
            As[lk + 3][lr + 16 * h] = va.w;

            float4 vb = *(const float4*)(brow[h] + kk + lk);
            Bs[lk + 0][lr + 16 * h] = vb.x;
            Bs[lk + 1][lr + 16 * h] = vb.y;
            Bs[lk + 2][lr + 16 * h] = vb.z;
            Bs[lk + 3][lr + 16 * h] = vb.w;
        }
        __syncthreads();
#pragma unroll
        for (int k = 0; k < 32; ++k) {
            float2 av = *(const float2*)&As[k][ty * 2];
            float4 bv = *(const float4*)&Bs[k][tx * 4];
            acc[0][0] = fmaxf(acc[0][0], av.x + bv.x);
            acc[0][1] = fmaxf(acc[0][1], av.x + bv.y);
            acc[0][2] = fmaxf(acc[0][2], av.x + bv.z);
            acc[0][3] = fmaxf(acc[0][3], av.x + bv.w);
            acc[1][0] = fmaxf(acc[1][0], av.y + bv.x);
            acc[1][1] = fmaxf(acc[1][1], av.y + bv.y);
            acc[1][2] = fmaxf(acc[1][2], av.y + bv.z);
            acc[1][3] = fmaxf(acc[1][3], av.y + bv.w);
        }
        __syncthreads();
    }

    // ---- epilogue ----
    const bool atomicMode = (MODE == M_EMBED || MODE == M_ATT || MODE == M_FF2);
    float rsub[2] = { 0.f, 0.f };
    if (MODE == M_QKV || MODE == M_FF1) {
        int r0 = bm + ty * 2;
        rsub[0] = rmSub[min(r0, M - 1)];
        rsub[1] = rmSub[min(r0 + 1, M - 1)];
    }
    const float tauv = (MODE == M_FF1) ? aux[0] : 0.f;
    float* Ch = (half ? C1 : C0) + (long)batch * cBatch;

    float rmax2[2] = { NEG_INF, NEG_INF };
#pragma unroll
    for (int i = 0; i < 2; ++i) {
        int m = bm + ty * 2 + i;
        bool ok = (m < M);
#pragma unroll
        for (int j = 0; j < 4; ++j) {
            int n = bn + tx * 4 + j;
            float v = acc[i][j];
            if (MODE == M_EMBED) v += aux[(m % NPATCH) * DD + n];
            if (MODE == M_QKV || MODE == M_FF1) v -= rsub[i];
            if (MODE == M_FF1) v = fmaxf(v, tauv);
            if (atomicMode) rmax2[i] = fmaxf(rmax2[i], v);
            if (!ok) continue;
            if (MODE == M_QKV) {
                if (n < DD)            C0[(long)m * DD + n] = v;
                else if (n < 2 * DD)   C1[(long)m * DD + (n - DD)] = v;
                else {
                    int b = m / NPATCH, ii = m % NPATCH;
                    C2[((long)b * DD + (n - 2 * DD)) * NPAD + ii] = v;
                }
            } else if (MODE == M_SCORES) {
                Ch[(long)m * ldc + n] = (n < N) ? v : NEG_INF;
            } else {
                Ch[(long)m * ldc + n] = v;
            }
        }
    }

    if (atomicMode) {
#pragma unroll
        for (int i = 0; i < 2; ++i) {
            float rm = rmax2[i];
#pragma unroll
            for (int o = 1; o < 8; o <<= 1)
                rm = fmaxf(rm, __shfl_xor_sync(0xffffffffu, rm, o));
            int m = bm + ty * 2 + i;
            if (tx == 0 && m < M) {
                int row = (MODE == M_ATT) ? batch * NPATCH + m : m;
                atomicMax(&rmAtom[row], f2ord(rm));
            }
        }
    }
}

// h = max(p0,p1); rmH = decode(atomic)     (single pass, no barrier)
__global__ void combine2_k(const float* __restrict__ p0, const float* __restrict__ p1,
                           const unsigned* __restrict__ rmSrc,
                           float* __restrict__ h, float* __restrict__ rmH)
{
    int r = blockIdx.x, t = threadIdx.x;
    long idx = (long)r * DD + t;
    h[idx] = fmaxf(p0[idx], p1[idx]);
    if (t == 0) rmH[r] = ord2f(rmSrc[r]);
}

// h = max(h, max(p0,p1) - rmA[r]); rmH = max(rmH,0); optional pool atomic
__global__ void resid2_k(const float* __restrict__ p0, const float* __restrict__ p1,
                         const unsigned* __restrict__ rmA,
                         float* __restrict__ h, float* __restrict__ rmH,
                         unsigned* __restrict__ poolAtom)
{
    int r = blockIdx.x, t = threadIdx.x;
    long idx = (long)r * DD + t;
    float av = fmaxf(p0[idx], p1[idx]);
    float hv = fmaxf(h[idx], av - ord2f(rmA[r]));
    h[idx] = hv;
    if (t == 0) rmH[r] = fmaxf(rmH[r], 0.f);
    if (poolAtom) atomicMax(&poolAtom[(r / NPATCH) * DD + t], f2ord(hv));
}

// logits[b,c] = max_d(pooled[b,d] + W[c,d]) * ls
__global__ void head_k(const float* __restrict__ W, const float* __restrict__ ls,
                       const unsigned* __restrict__ poolAtom, float* __restrict__ out)
{
    __shared__ float p[DD];
    int b = blockIdx.y, t = threadIdx.x;
    p[t] = ord2f(poolAtom[b * DD + t]);
    __syncthreads();
    int c = blockIdx.x * 128 + t;
    if (c < NCLS) {
        float acc = NEG_INF;
        const float* w = W + (long)c * DD;
#pragma unroll 4
        for (int d = 0; d < DD; ++d) acc = fmaxf(acc, p[d] + w[d]);
        out[(long)b * NCLS + c] = acc * ls[0];
    }
}

// ---------------------------------------------------------------------------

extern "C" void kernel_launch(void* const* d_in, const int* in_sizes, int n_in,
                              void* d_out, int out_size)
{
    (void)in_sizes; (void)n_in; (void)out_size;
    const float* x       = (const float*)d_in[0];
    const float* embed_W = (const float*)d_in[1];
    const float* pos     = (const float*)d_in[2];
    const float* head_W  = (const float*)d_in[15];
    const float* lscale  = (const float*)d_in[16];
    float* out = (float*)d_out;

    float *h, *rmH, *q, *k, *vT, *s, *p, *h1;
    unsigned* at;
    cudaGetSymbolAddress((void**)&h,   g_h);
    cudaGetSymbolAddress((void**)&rmH, g_rmH);
    cudaGetSymbolAddress((void**)&q,   g_q);
    cudaGetSymbolAddress((void**)&k,   g_k);
    cudaGetSymbolAddress((void**)&vT,  g_vT);
    cudaGetSymbolAddress((void**)&s,   g_s);
    cudaGetSymbolAddress((void**)&p,   g_p);
    cudaGetSymbolAddress((void**)&h1,  g_h1);
    cudaGetSymbolAddress((void**)&at,  g_atoms);

    float* p1 = p + MTOT * DD;
    unsigned* rmE     = at;
    unsigned* poolAt  = at + 5 * MTOT;

    cudaMemsetAsync(at, 0, (5 * MTOT + BB * DD) * sizeof(unsigned));

    // embed: patchify fused, K=256 split2 -> p0/p1 ; +pos & rowmax in epilogue
    tg<M_EMBED><<<dim3(4, 49, 2), 128>>>(x, embed_W, 0, 0, p, p1, 0,
        0, rmE, pos, MTOT, DD, 256, DD, 0, 0, 0, 1, 128);
    combine2_k<<<MTOT, 128>>>(p, p1, rmE, h, rmH);

    for (int l = 0; l < 2; ++l) {
        const float* qW  = (const float*)d_in[3 + 6 * l];
        const float* kW  = (const float*)d_in[4 + 6 * l];
        const float* vW  = (const float*)d_in[5 + 6 * l];
        const float* f1W = (const float*)d_in[6 + 6 * l];
        const float* f2W = (const float*)d_in[7 + 6 * l];
        const float* tau = (const float*)d_in[8 + 6 * l];
        unsigned* rmAt = at + (1 + 2 * l) * MTOT;
        unsigned* rmFf = at + (2 + 2 * l) * MTOT;

        // q/k/v fused (N=384): A=h, epilogue subtracts rmH
        tg<M_QKV><<<dim3(12, 49, 1), 128>>>(h, qW, kW, vW, q, k, vT,
            rmH, 0, 0, MTOT, 384, DD, 0, 0, 0, 0, 0, DD);

        // scores per batch: (196x128) x (196x128)^T -> (196 x 224), pads -inf
        tg<M_SCORES><<<dim3(7, 7, 8), 128>>>(q, k, 0, 0, s, 0, 0,
            0, 0, 0, NPATCH, NPATCH, DD, NPAD,
            NPATCH * DD, NPATCH * DD, NPATCH * NPAD, 0, DD);

        // attn out per batch: K=224 split2 -> p0/p1 + atomic rowmax
        tg<M_ATT><<<dim3(4, 7, 16), 128>>>(s, vT, 0, 0, p, p1, 0,
            0, rmAt, 0, NPATCH, DD, NPAD, DD,
            NPATCH * NPAD, DD * NPAD, NPATCH * DD, 1, 128);
        resid2_k<<<MTOT, 128>>>(p, p1, rmAt, h, rmH, 0);

        // ff1: A=h, epilogue subtracts rmH then max(tau) -> h1
        tg<M_FF1><<<dim3(8, 49, 1), 128>>>(h, f1W, 0, 0, h1, 0, 0,
            rmH, 0, tau, MTOT, DFF, DD, DFF, 0, 0, 0, 0, DD);

        // ff2: K=256 split2 -> p0/p1 + atomic rowmax
        tg<M_FF2><<<dim3(4, 49, 2), 128>>>(h1, f2W, 0, 0, p, p1, 0,
            0, rmFf, 0, MTOT, DD, DFF, DD, 0, 0, 0, 1, 128);
        resid2_k<<<MTOT, 128>>>(p, p1, rmFf, h, rmH,
                                (l == 1) ? poolAt : 0);
    }

    head_k<<<dim3(8, BB), 128>>>(head_W, lscale, poolAt, out);
}